// round 12
// baseline (speedup 1.0000x reference)
#include <cuda_runtime.h>
#include <climits>

#define BB   2
#define NPTS 16384
#define MQ   4096
#define CIN  16
#define KNB  32
#define RAD2 0.01f
#define EPSV 1e-8f
#define FULLM 0xFFFFFFFFu
#define G    10
#define NCELL (G*G*G)
#define CAP  256
#define NQ   (BB * MQ)
#define PBLK 608   /* 152 SMs * 4 blocks */

__device__ int    g_cnt[BB * NCELL];
__device__ int    g_start[BB * NCELL];
__device__ float4 g_pts[BB * NPTS];
__device__ float  g_featg[(size_t)BB * NPTS * CIN];   // grid-ordered [pos][16]
__device__ int    g_work;

// ---------------- packed f32x2 helpers ----------------
__device__ __forceinline__ unsigned long long fma2(unsigned long long a,
                                                   unsigned long long b,
                                                   unsigned long long c) {
    unsigned long long d;
    asm("fma.rn.f32x2 %0, %1, %2, %3;" : "=l"(d) : "l"(a), "l"(b), "l"(c));
    return d;
}
__device__ __forceinline__ unsigned long long pack2(float x, float y) {
    unsigned long long r;
    asm("mov.b64 %0, {%1,%2};" : "=l"(r) : "f"(x), "f"(y));
    return r;
}
__device__ __forceinline__ void unpack2(float& x, float& y, unsigned long long v) {
    asm("mov.b64 {%0,%1}, %2;" : "=f"(x), "=f"(y) : "l"(v));
}

__device__ __forceinline__ int cellOf(float x, float y, float z) {
    int cx = min((int)(x * (float)G), G - 1);
    int cy = min((int)(y * (float)G), G - 1);
    int cz = min((int)(z * (float)G), G - 1);
    return (cx * G + cy) * G + cz;
}

__global__ void hist_kernel(const float* __restrict__ xyz) {
    int p = blockIdx.x * blockDim.x + threadIdx.x;
    if (p == 0) g_work = 0;                 // reset grouper work counter
    if (p >= BB * NPTS) return;
    int b = p / NPTS;
    float x = xyz[3 * p + 0], y = xyz[3 * p + 1], z = xyz[3 * p + 2];
    atomicAdd(&g_cnt[b * NCELL + cellOf(x, y, z)], 1);
}

__global__ void scan_kernel() {   // one block per batch
    __shared__ int s[1024];
    int b = blockIdx.x, i = threadIdx.x;
    int val = (i < NCELL) ? g_cnt[b * NCELL + i] : 0;
    s[i] = val;
    __syncthreads();
    #pragma unroll
    for (int off = 1; off < 1024; off <<= 1) {
        int t = (i >= off) ? s[i - off] : 0;
        __syncthreads();
        s[i] += t;
        __syncthreads();
    }
    if (i < NCELL) {
        g_start[b * NCELL + i] = s[i] - val;   // exclusive
        g_cnt[b * NCELL + i] = 0;              // reuse as scatter counter
    }
}

// 4 threads per point (one per channel-quad); pos computed once, shfl-broadcast
__global__ void scatter_feat_kernel(const float* __restrict__ xyz,
                                    const float* __restrict__ features) {
    int t = blockIdx.x * blockDim.x + threadIdx.x;
    int p = t >> 2, qd = t & 3;
    if (p >= BB * NPTS) return;
    int b = p / NPTS, i = p % NPTS;
    int lane = threadIdx.x & 31;

    int pos = 0;
    if (qd == 0) {
        float x = xyz[3 * p + 0], y = xyz[3 * p + 1], z = xyz[3 * p + 2];
        int c = b * NCELL + cellOf(x, y, z);
        pos = g_start[c] + atomicAdd(&g_cnt[c], 1);
        g_pts[b * NPTS + pos] = make_float4(x, y, z, __int_as_float(i));
    }
    pos = __shfl_sync(FULLM, pos, lane & ~3);

    const float* fb = features + (size_t)b * CIN * NPTS + i;
    float v0 = __ldg(fb + (size_t)(qd * 4 + 0) * NPTS);
    float v1 = __ldg(fb + (size_t)(qd * 4 + 1) * NPTS);
    float v2 = __ldg(fb + (size_t)(qd * 4 + 2) * NPTS);
    float v3 = __ldg(fb + (size_t)(qd * 4 + 3) * NPTS);
    ((float4*)(g_featg + ((size_t)b * NPTS + pos) * CIN))[qd] =
        make_float4(v0, v1, v2, v3);
}

__device__ __forceinline__ float warpSum(float v) {
    #pragma unroll
    for (int o = 16; o > 0; o >>= 1) v += __shfl_xor_sync(FULLM, v, o);
    return v;
}

__global__ __launch_bounds__(256, 4) void grouper_kernel(
    const float* __restrict__ xyz, const float* __restrict__ new_xyz,
    const float* __restrict__ w0, const float* __restrict__ b0,
    const float* __restrict__ w1, const float* __restrict__ b1,
    const float* __restrict__ wxyz, const float* __restrict__ bxyz,
    float* __restrict__ feat_out)
{
    // pair-interleaved weights for packed f32x2
    __shared__ ulonglong2 s_w0p[16 * 8];    // 2 KB
    __shared__ ulonglong2 s_w1p[32 * 16];   // 8 KB
    __shared__ unsigned long long s_wxp[48], s_bxp[16];
    __shared__ float s_b0[32], s_b1[64];
    __shared__ int   s_cand[8][CAP];

    int tid = threadIdx.x;
    {
        float* f0 = (float*)s_w0p;
        for (int e = tid; e < 512; e += 256) {
            int qq = e & 3, c2 = (e >> 2) & 7, p = e >> 5;
            f0[e] = w0[(2 * p + (qq & 1)) * 16 + 2 * c2 + (qq >> 1)];
        }
        float* f1 = (float*)s_w1p;
        for (int e = tid; e < 2048; e += 256) {
            int qq = e & 3, c2 = (e >> 2) & 15, p = e >> 6;
            f1[e] = w1[(2 * p + (qq & 1)) * 32 + 2 * c2 + (qq >> 1)];
        }
        float* fx = (float*)s_wxp;   // [d][t] pairs: (wx[2t][d], wx[2t+1][d])
        if (tid < 96) {
            int qq = tid & 1, t = (tid >> 1) & 15, d = tid >> 5;
            fx[d * 32 + t * 2 + qq] = wxyz[(2 * t + qq) * 3 + d];
        }
        float* fbx = (float*)s_bxp;
        if (tid < 32) fbx[tid] = bxyz[tid];
    }
    if (tid < 32) s_b0[tid] = b0[tid];
    if (tid < 64) s_b1[tid] = b1[tid];
    __syncthreads();

    int warp = tid >> 5, lane = tid & 31;
    unsigned laneLT = (1u << lane) - 1u;
    int* lst = s_cand[warp];

    // ---- persistent warp with software-pipelined work-steal
    int q;
    if (lane == 0) q = atomicAdd(&g_work, 1);
    q = __shfl_sync(FULLM, q, 0);

    while (q < NQ) {
        int qn = 0;
        if (lane == 0) qn = atomicAdd(&g_work, 1);   // prefetch NEXT query id

        int b = q / MQ, m = q % MQ;
        const float* qp = new_xyz + ((size_t)b * MQ + m) * 3;
        float qx = __ldg(qp + 0), qy = __ldg(qp + 1), qz = __ldg(qp + 2);

        int qcx = min((int)(qx * (float)G), G - 1);
        int qcy = min((int)(qy * (float)G), G - 1);

        // prefetch all 9 column ranges in parallel (lanes 0..8)
        int colS = 0, colE = 0;
        if (lane < 9) {
            int cx = qcx + lane / 3 - 1, cy = qcy + lane % 3 - 1;
            if (cx >= 0 && cx < G && cy >= 0 && cy < G) {
                float fx = fmaxf(0.f, fmaxf(cx * 0.1f - qx, qx - (cx + 1) * 0.1f));
                float fy = fmaxf(0.f, fmaxf(cy * 0.1f - qy, qy - (cy + 1) * 0.1f));
                float dxy2 = fx * fx + fy * fy;
                if (dxy2 < RAD2) {
                    float rzs = sqrtf(RAD2 - dxy2) + 1e-6f;
                    int zz0 = max(0, (int)((qz - rzs) * (float)G));
                    int zz1 = min(G - 1, (int)((qz + rzs) * (float)G));
                    int cbase = b * NCELL + (cx * G + cy) * G;
                    colS = g_start[cbase + zz0];
                    colE = g_start[cbase + zz1] + g_cnt[cbase + zz1];
                }
            }
        }

        // candidate collection: key = (origIdx << 14) | gridPos
        int cnt = 0;
        const float4* pb = g_pts + (size_t)b * NPTS;

        for (int cc = 0; cc < 9; cc++) {
            int s = __shfl_sync(FULLM, colS, cc);
            int e = __shfl_sync(FULLM, colE, cc);
            for (int base = s; base < e; base += 32) {
                int i = base + lane;
                bool hit = false; int key = 0;
                if (i < e) {
                    float4 p = __ldg(&pb[i]);
                    float dx = p.x - qx, dy = p.y - qy, dz = p.z - qz;
                    hit = (dx * dx + dy * dy + dz * dz) < RAD2;
                    key = (__float_as_int(p.w) << 14) | i;
                }
                unsigned mk = __ballot_sync(FULLM, hit);
                if (hit) {
                    int pos = cnt + __popc(mk & laneLT);
                    if (pos < CAP) lst[pos] = key;
                }
                cnt += __popc(mk);
            }
        }
        cnt = min(cnt, CAP);
        __syncwarp();

        // load candidates (orig indices DISTINCT)
        int c[8];
        #pragma unroll
        for (int j = 0; j < 8; j++) {
            int p = lane + 32 * j;
            c[j] = (p < cnt) ? lst[p] : INT_MAX;
        }
        int mn8 = c[0];
        #pragma unroll
        for (int j = 1; j < 8; j++) mn8 = min(mn8, c[j]);
        int firstKey = __reduce_min_sync(FULLM, mn8);
        bool hasAny = (cnt > 0);

        int sel;
        if (cnt > KNB) {
            int o[8];
            #pragma unroll
            for (int j = 0; j < 8; j++) o[j] = c[j] >> 14;
            int lo = 0, hi = NPTS - 1;                   // threshold on orig index
            while (lo < hi) {
                int mid = (lo + hi) >> 1;
                int lc = 0;
                #pragma unroll
                for (int j = 0; j < 8; j++) lc += (o[j] <= mid);
                int tot = __reduce_add_sync(FULLM, (unsigned)lc);
                if (tot >= KNB) hi = mid; else lo = mid + 1;
            }
            int T = lo;
            __syncwarp();
            int base2 = 0;
            #pragma unroll
            for (int j = 0; j < 8; j++) {
                bool sflag = (o[j] <= T);
                unsigned mk = __ballot_sync(FULLM, sflag);
                if (sflag) lst[base2 + __popc(mk & laneLT)] = c[j];
                base2 += __popc(mk);
            }
            __syncwarp();
            sel = lst[lane];
        } else {
            sel = (lane < cnt) ? lst[lane] : firstKey;   // pad with smallest
        }

        int idn = __popc(__match_any_sync(FULLM, sel));
        int pos = sel & (NPTS - 1);

        // coords from grid-ordered points
        float px, py, pz;
        if (hasAny) {
            float4 p = __ldg(&pb[pos]);
            px = p.x; py = p.y; pz = p.z;
        } else {
            const float* xb = xyz + (size_t)b * NPTS * 3;  // reference: idx = 0
            px = __ldg(xb + 0); py = __ldg(xb + 1); pz = __ldg(xb + 2);
        }
        float rx = px - qx, ry = py - qy, rz = pz - qz;
        float dist = sqrtf(rx * rx + ry * ry + rz * rz);
        float dr = 1.0f / (dist + EPSV);
        dr = dr / (hasAny ? (float)idn : 1.0f);
        float drsum = warpSum(dr);
        float w = hasAny ? (dr / drsum) : 0.0f;

        // gather features
        float g[CIN];
        {
            const float4* gp = (const float4*)(g_featg + ((size_t)b * NPTS + pos) * CIN);
            float4 f0 = __ldg(gp + 0), f1 = __ldg(gp + 1);
            float4 f2 = __ldg(gp + 2), f3 = __ldg(gp + 3);
            g[0]=f0.x; g[1]=f0.y; g[2]=f0.z; g[3]=f0.w;
            g[4]=f1.x; g[5]=f1.y; g[6]=f1.z; g[7]=f1.w;
            g[8]=f2.x; g[9]=f2.y; g[10]=f2.z; g[11]=f2.w;
            g[12]=f3.x; g[13]=f3.y; g[14]=f3.z; g[15]=f3.w;
        }

        float* fo = feat_out + (size_t)b * 96 * MQ + m;

        // xyz branch: 3->32 packed fma2, then butterfly MAX fold
        {
            unsigned long long hrx = pack2(rx, rx), hry = pack2(ry, ry), hrz = pack2(rz, rz);
            float v[32];
            #pragma unroll
            for (int t = 0; t < 16; t++) {
                unsigned long long a = fma2(s_wxp[t], hrx, s_bxp[t]);
                a = fma2(s_wxp[16 + t], hry, a);
                a = fma2(s_wxp[32 + t], hrz, a);
                float xa, xb2; unpack2(xa, xb2, a);
                v[2 * t] = fmaxf(xa, 0.0f);
                v[2 * t + 1] = fmaxf(xb2, 0.0f);
            }
            {
                bool h = (lane >> 4) & 1;
                #pragma unroll
                for (int i = 0; i < 16; i++) {
                    float keep = h ? v[i + 16] : v[i];
                    float snd  = h ? v[i]      : v[i + 16];
                    v[i] = fmaxf(keep, __shfl_xor_sync(FULLM, snd, 16));
                }
            }
            {
                bool h = (lane >> 3) & 1;
                #pragma unroll
                for (int i = 0; i < 8; i++) {
                    float keep = h ? v[i + 8] : v[i];
                    float snd  = h ? v[i]     : v[i + 8];
                    v[i] = fmaxf(keep, __shfl_xor_sync(FULLM, snd, 8));
                }
            }
            {
                bool h = (lane >> 2) & 1;
                #pragma unroll
                for (int i = 0; i < 4; i++) {
                    float keep = h ? v[i + 4] : v[i];
                    float snd  = h ? v[i]     : v[i + 4];
                    v[i] = fmaxf(keep, __shfl_xor_sync(FULLM, snd, 4));
                }
            }
            {
                bool h = (lane >> 1) & 1;
                #pragma unroll
                for (int i = 0; i < 2; i++) {
                    float keep = h ? v[i + 2] : v[i];
                    float snd  = h ? v[i]     : v[i + 2];
                    v[i] = fmaxf(keep, __shfl_xor_sync(FULLM, snd, 2));
                }
            }
            {
                bool h = lane & 1;
                float keep = h ? v[1] : v[0];
                float snd  = h ? v[0] : v[1];
                v[0] = fmaxf(keep, __shfl_xor_sync(FULLM, snd, 1));
            }
            fo[(size_t)lane * MQ] = v[0];    // lane l holds channel l
        }

        // layer 0: 16 -> 32, packed f32x2
        float h0[32];
        {
            unsigned long long acc0[16];
            #pragma unroll
            for (int t = 0; t < 16; t++) acc0[t] = pack2(s_b0[2 * t], s_b0[2 * t + 1]);
            #pragma unroll
            for (int c2 = 0; c2 < 8; c2++) {
                unsigned long long ha = pack2(g[2 * c2],     g[2 * c2]);
                unsigned long long hb = pack2(g[2 * c2 + 1], g[2 * c2 + 1]);
                #pragma unroll
                for (int t = 0; t < 16; t++) {
                    ulonglong2 wv = s_w0p[t * 8 + c2];
                    acc0[t] = fma2(wv.x, ha, acc0[t]);
                    acc0[t] = fma2(wv.y, hb, acc0[t]);
                }
            }
            #pragma unroll
            for (int t = 0; t < 16; t++) {
                float a, bqq; unpack2(a, bqq, acc0[t]);
                h0[2 * t] = fmaxf(a, 0.0f);
                h0[2 * t + 1] = fmaxf(bqq, 0.0f);
            }
        }

        // layer 1: 32 -> 64 in 4 chunks, packed FMA + butterfly SUM fold
        #pragma unroll
        for (int og = 0; og < 4; og++) {
            unsigned long long acc[8];
            #pragma unroll
            for (int t = 0; t < 8; t++)
                acc[t] = pack2(s_b1[og * 16 + 2 * t], s_b1[og * 16 + 2 * t + 1]);
            #pragma unroll
            for (int c2 = 0; c2 < 16; c2++) {
                unsigned long long ha = pack2(h0[2 * c2],     h0[2 * c2]);
                unsigned long long hb = pack2(h0[2 * c2 + 1], h0[2 * c2 + 1]);
                #pragma unroll
                for (int t = 0; t < 8; t++) {
                    ulonglong2 wv = s_w1p[(og * 8 + t) * 16 + c2];
                    acc[t] = fma2(wv.x, ha, acc[t]);
                    acc[t] = fma2(wv.y, hb, acc[t]);
                }
            }
            float v[16];
            #pragma unroll
            for (int t = 0; t < 8; t++) {
                float a, bqq; unpack2(a, bqq, acc[t]);
                v[2 * t]     = w * fmaxf(a, 0.0f);
                v[2 * t + 1] = w * fmaxf(bqq, 0.0f);
            }
            #pragma unroll
            for (int i = 0; i < 16; i++) v[i] += __shfl_xor_sync(FULLM, v[i], 16);
            {
                bool h = (lane >> 3) & 1;
                #pragma unroll
                for (int i = 0; i < 8; i++) {
                    float keep = h ? v[i + 8] : v[i];
                    float snd  = h ? v[i]     : v[i + 8];
                    v[i] = keep + __shfl_xor_sync(FULLM, snd, 8);
                }
            }
            {
                bool h = (lane >> 2) & 1;
                #pragma unroll
                for (int i = 0; i < 4; i++) {
                    float keep = h ? v[i + 4] : v[i];
                    float snd  = h ? v[i]     : v[i + 4];
                    v[i] = keep + __shfl_xor_sync(FULLM, snd, 4);
                }
            }
            {
                bool h = (lane >> 1) & 1;
                #pragma unroll
                for (int i = 0; i < 2; i++) {
                    float keep = h ? v[i + 2] : v[i];
                    float snd  = h ? v[i]     : v[i + 2];
                    v[i] = keep + __shfl_xor_sync(FULLM, snd, 2);
                }
            }
            {
                bool h = lane & 1;
                float keep = h ? v[1] : v[0];
                float snd  = h ? v[0] : v[1];
                v[0] = keep + __shfl_xor_sync(FULLM, snd, 1);
            }
            if (lane < 16)
                fo[(size_t)(32 + og * 16 + lane) * MQ] = v[0];
        }

        q = __shfl_sync(FULLM, qn, 0);   // consume prefetched id (latency hidden)
    }
}

extern "C" void kernel_launch(void* const* d_in, const int* in_sizes, int n_in,
                              void* d_out, int out_size) {
    const float* xyz      = (const float*)d_in[0];
    const float* new_xyz  = (const float*)d_in[1];
    const float* features = (const float*)d_in[2];
    const float* w0   = (const float*)d_in[3];
    const float* b0   = (const float*)d_in[4];
    const float* w1   = (const float*)d_in[5];
    const float* b1   = (const float*)d_in[6];
    const float* wxyz = (const float*)d_in[7];
    const float* bxyz = (const float*)d_in[8];

    float* out = (float*)d_out;
    long nxyz  = (long)BB * MQ * 3;
    long nfeat = (long)BB * 96 * MQ;
    float* feat_out;
    if ((long)out_size >= nxyz + nfeat) {
        cudaMemcpyAsync(out, new_xyz, nxyz * sizeof(float),
                        cudaMemcpyDeviceToDevice);
        feat_out = out + nxyz;
    } else {
        feat_out = out;
    }

    void* cnt_ptr = nullptr;
    cudaGetSymbolAddress(&cnt_ptr, g_cnt);
    cudaMemsetAsync(cnt_ptr, 0, BB * NCELL * sizeof(int));

    hist_kernel<<<(BB * NPTS + 255) / 256, 256>>>(xyz);
    scan_kernel<<<BB, 1024>>>();
    scatter_feat_kernel<<<(BB * NPTS * 4 + 255) / 256, 256>>>(xyz, features);
    grouper_kernel<<<PBLK, 256>>>(xyz, new_xyz,
                                  w0, b0, w1, b1, wxyz, bxyz, feat_out);
}

// round 13
// speedup vs baseline: 1.0272x; 1.0272x over previous
#include <cuda_runtime.h>
#include <climits>

#define BB   2
#define NPTS 16384
#define MQ   4096
#define CIN  16
#define KNB  32
#define RAD2 0.01f
#define EPSV 1e-8f
#define FULLM 0xFFFFFFFFu
#define G    10
#define NCELL (G*G*G)
#define CAP  256
#define NQ   (BB * MQ)

__device__ int    g_cnt[BB * NCELL];
__device__ int    g_start[BB * NCELL];
__device__ int    g_qcnt[BB * NCELL];
__device__ int    g_qstart[BB * NCELL];
__device__ int    g_qorder[NQ];
__device__ float4 g_pts[BB * NPTS];
__device__ float  g_featg[(size_t)BB * NPTS * CIN];   // grid-ordered [pos][16]

// ---------------- packed f32x2 helpers ----------------
__device__ __forceinline__ unsigned long long fma2(unsigned long long a,
                                                   unsigned long long b,
                                                   unsigned long long c) {
    unsigned long long d;
    asm("fma.rn.f32x2 %0, %1, %2, %3;" : "=l"(d) : "l"(a), "l"(b), "l"(c));
    return d;
}
__device__ __forceinline__ unsigned long long pack2(float x, float y) {
    unsigned long long r;
    asm("mov.b64 %0, {%1,%2};" : "=l"(r) : "f"(x), "f"(y));
    return r;
}
__device__ __forceinline__ void unpack2(float& x, float& y, unsigned long long v) {
    asm("mov.b64 {%0,%1}, %2;" : "=f"(x), "=f"(y) : "l"(v));
}

__device__ __forceinline__ int cellOf(float x, float y, float z) {
    int cx = min((int)(x * (float)G), G - 1);
    int cy = min((int)(y * (float)G), G - 1);
    int cz = min((int)(z * (float)G), G - 1);
    return (cx * G + cy) * G + cz;
}

// histogram points AND queries by cell
__global__ void hist_kernel(const float* __restrict__ xyz,
                            const float* __restrict__ new_xyz) {
    int p = blockIdx.x * blockDim.x + threadIdx.x;
    if (p < BB * NPTS) {
        int b = p / NPTS;
        float x = xyz[3 * p + 0], y = xyz[3 * p + 1], z = xyz[3 * p + 2];
        atomicAdd(&g_cnt[b * NCELL + cellOf(x, y, z)], 1);
    } else {
        int j = p - BB * NPTS;
        if (j < NQ) {
            int b = j / MQ;
            float x = new_xyz[3 * j + 0], y = new_xyz[3 * j + 1], z = new_xyz[3 * j + 2];
            atomicAdd(&g_qcnt[b * NCELL + cellOf(x, y, z)], 1);
        }
    }
}

__global__ void scan_kernel() {   // one block per batch: scan points, then queries
    __shared__ int s[1024];
    int b = blockIdx.x, i = threadIdx.x;
    // pass 1: point histogram
    int val = (i < NCELL) ? g_cnt[b * NCELL + i] : 0;
    s[i] = val;
    __syncthreads();
    #pragma unroll
    for (int off = 1; off < 1024; off <<= 1) {
        int t = (i >= off) ? s[i - off] : 0;
        __syncthreads();
        s[i] += t;
        __syncthreads();
    }
    if (i < NCELL) {
        g_start[b * NCELL + i] = s[i] - val;   // exclusive
        g_cnt[b * NCELL + i] = 0;              // reuse as scatter counter
    }
    __syncthreads();
    // pass 2: query histogram
    int qval = (i < NCELL) ? g_qcnt[b * NCELL + i] : 0;
    s[i] = qval;
    __syncthreads();
    #pragma unroll
    for (int off = 1; off < 1024; off <<= 1) {
        int t = (i >= off) ? s[i - off] : 0;
        __syncthreads();
        s[i] += t;
        __syncthreads();
    }
    if (i < NCELL) {
        g_qstart[b * NCELL + i] = s[i] - qval;
        g_qcnt[b * NCELL + i] = 0;
    }
}

// scatter points (with features, grid-ordered) AND query ids (cell-sorted)
__global__ void scatter_feat_kernel(const float* __restrict__ xyz,
                                    const float* __restrict__ new_xyz,
                                    const float* __restrict__ features) {
    int p = blockIdx.x * blockDim.x + threadIdx.x;
    if (p < BB * NPTS) {
        int b = p / NPTS, i = p % NPTS;
        float x = xyz[3 * p + 0], y = xyz[3 * p + 1], z = xyz[3 * p + 2];
        int c = b * NCELL + cellOf(x, y, z);
        int pos = g_start[c] + atomicAdd(&g_cnt[c], 1);
        g_pts[b * NPTS + pos] = make_float4(x, y, z, __int_as_float(i));

        const float* fb = features + (size_t)b * CIN * NPTS + i;
        float v[CIN];
        #pragma unroll
        for (int cc = 0; cc < CIN; cc++) v[cc] = __ldg(fb + (size_t)cc * NPTS);
        float4* dst = (float4*)(g_featg + ((size_t)b * NPTS + pos) * CIN);
        dst[0] = make_float4(v[0],  v[1],  v[2],  v[3]);
        dst[1] = make_float4(v[4],  v[5],  v[6],  v[7]);
        dst[2] = make_float4(v[8],  v[9],  v[10], v[11]);
        dst[3] = make_float4(v[12], v[13], v[14], v[15]);
    } else {
        int j = p - BB * NPTS;
        if (j < NQ) {
            int b = j / MQ, m = j % MQ;
            float x = new_xyz[3 * j + 0], y = new_xyz[3 * j + 1], z = new_xyz[3 * j + 2];
            int c = b * NCELL + cellOf(x, y, z);
            int pos = g_qstart[c] + atomicAdd(&g_qcnt[c], 1);
            g_qorder[b * MQ + pos] = m;
        }
    }
}

__device__ __forceinline__ float warpSum(float v) {
    #pragma unroll
    for (int o = 16; o > 0; o >>= 1) v += __shfl_xor_sync(FULLM, v, o);
    return v;
}

__global__ __launch_bounds__(256, 4) void grouper_kernel(
    const float* __restrict__ xyz, const float* __restrict__ new_xyz,
    const float* __restrict__ w0, const float* __restrict__ b0,
    const float* __restrict__ w1, const float* __restrict__ b1,
    const float* __restrict__ wxyz, const float* __restrict__ bxyz,
    float* __restrict__ feat_out)
{
    // pair-interleaved weights for packed f32x2
    __shared__ ulonglong2 s_w0p[16 * 8];    // 2 KB
    __shared__ ulonglong2 s_w1p[32 * 16];   // 8 KB
    __shared__ unsigned long long s_wxp[48], s_bxp[16];
    __shared__ float s_b0[32], s_b1[64];
    __shared__ int   s_cand[8][CAP];

    int tid = threadIdx.x;
    {
        float* f0 = (float*)s_w0p;
        for (int e = tid; e < 512; e += 256) {
            int qq = e & 3, c2 = (e >> 2) & 7, p = e >> 5;
            f0[e] = w0[(2 * p + (qq & 1)) * 16 + 2 * c2 + (qq >> 1)];
        }
        float* f1 = (float*)s_w1p;
        for (int e = tid; e < 2048; e += 256) {
            int qq = e & 3, c2 = (e >> 2) & 15, p = e >> 6;
            f1[e] = w1[(2 * p + (qq & 1)) * 32 + 2 * c2 + (qq >> 1)];
        }
        float* fx = (float*)s_wxp;   // [d][t] pairs: (wx[2t][d], wx[2t+1][d])
        if (tid < 96) {
            int qq = tid & 1, t = (tid >> 1) & 15, d = tid >> 5;
            fx[d * 32 + t * 2 + qq] = wxyz[(2 * t + qq) * 3 + d];
        }
        float* fbx = (float*)s_bxp;
        if (tid < 32) fbx[tid] = bxyz[tid];
    }
    if (tid < 32) s_b0[tid] = b0[tid];
    if (tid < 64) s_b1[tid] = b1[tid];
    __syncthreads();

    int warp = tid >> 5, lane = tid & 31;
    int qs = blockIdx.x * 8 + warp;       // cell-sorted slot
    int b = qs / MQ;
    int m = __ldg(&g_qorder[qs]);         // original query index within batch

    const float* qp = new_xyz + ((size_t)b * MQ + m) * 3;
    float qx = __ldg(qp + 0), qy = __ldg(qp + 1), qz = __ldg(qp + 2);

    int qcx = min((int)(qx * (float)G), G - 1);
    int qcy = min((int)(qy * (float)G), G - 1);

    // ---- prefetch all 9 column ranges in parallel (lanes 0..8)
    int colS = 0, colE = 0;
    if (lane < 9) {
        int cx = qcx + lane / 3 - 1, cy = qcy + lane % 3 - 1;
        if (cx >= 0 && cx < G && cy >= 0 && cy < G) {
            float fx = fmaxf(0.f, fmaxf(cx * 0.1f - qx, qx - (cx + 1) * 0.1f));
            float fy = fmaxf(0.f, fmaxf(cy * 0.1f - qy, qy - (cy + 1) * 0.1f));
            float dxy2 = fx * fx + fy * fy;
            if (dxy2 < RAD2) {
                float rzs = sqrtf(RAD2 - dxy2) + 1e-6f;
                int zz0 = max(0, (int)((qz - rzs) * (float)G));
                int zz1 = min(G - 1, (int)((qz + rzs) * (float)G));
                int cbase = b * NCELL + (cx * G + cy) * G;
                colS = g_start[cbase + zz0];
                colE = g_start[cbase + zz1] + g_cnt[cbase + zz1];
            }
        }
    }

    // ---- candidate collection: key = (origIdx << 14) | gridPos
    int* lst = s_cand[warp];
    int cnt = 0;
    const float4* pb = g_pts + (size_t)b * NPTS;
    unsigned laneLT = (1u << lane) - 1u;

    for (int cc = 0; cc < 9; cc++) {
        int s = __shfl_sync(FULLM, colS, cc);
        int e = __shfl_sync(FULLM, colE, cc);
        for (int base = s; base < e; base += 32) {
            int i = base + lane;
            bool hit = false; int key = 0;
            if (i < e) {
                float4 p = __ldg(&pb[i]);
                float dx = p.x - qx, dy = p.y - qy, dz = p.z - qz;
                hit = (dx * dx + dy * dy + dz * dz) < RAD2;
                key = (__float_as_int(p.w) << 14) | i;
            }
            unsigned mk = __ballot_sync(FULLM, hit);
            if (hit) {
                int pos = cnt + __popc(mk & laneLT);
                if (pos < CAP) lst[pos] = key;
            }
            cnt += __popc(mk);
        }
    }
    cnt = min(cnt, CAP);
    __syncwarp();

    // ---- load candidates (orig indices DISTINCT)
    int c[8];
    #pragma unroll
    for (int j = 0; j < 8; j++) {
        int p = lane + 32 * j;
        c[j] = (p < cnt) ? lst[p] : INT_MAX;
    }
    int mn8 = c[0];
    #pragma unroll
    for (int j = 1; j < 8; j++) mn8 = min(mn8, c[j]);
    int firstKey = __reduce_min_sync(FULLM, mn8);
    bool hasAny = (cnt > 0);

    int sel;
    if (cnt > KNB) {
        int o[8];
        #pragma unroll
        for (int j = 0; j < 8; j++) o[j] = c[j] >> 14;   // INT_MAX>>14 stays huge
        int lo = 0, hi = NPTS - 1;                       // threshold on orig index
        while (lo < hi) {
            int mid = (lo + hi) >> 1;
            int lc = 0;
            #pragma unroll
            for (int j = 0; j < 8; j++) lc += (o[j] <= mid);
            int tot = __reduce_add_sync(FULLM, (unsigned)lc);
            if (tot >= KNB) hi = mid; else lo = mid + 1;
        }
        int T = lo;
        __syncwarp();
        int base2 = 0;
        #pragma unroll
        for (int j = 0; j < 8; j++) {
            bool sflag = (o[j] <= T);
            unsigned mk = __ballot_sync(FULLM, sflag);
            if (sflag) lst[base2 + __popc(mk & laneLT)] = c[j];
            base2 += __popc(mk);
        }
        __syncwarp();
        sel = lst[lane];
    } else {
        sel = (lane < cnt) ? lst[lane] : firstKey;       // pad with smallest
    }

    int idn = __popc(__match_any_sync(FULLM, sel));
    int pos = sel & (NPTS - 1);

    // ---- coords from grid-ordered points
    float px, py, pz;
    if (hasAny) {
        float4 p = __ldg(&pb[pos]);
        px = p.x; py = p.y; pz = p.z;
    } else {
        const float* xb = xyz + (size_t)b * NPTS * 3;    // reference: idx = 0
        px = __ldg(xb + 0); py = __ldg(xb + 1); pz = __ldg(xb + 2);
    }
    float rx = px - qx, ry = py - qy, rz = pz - qz;
    float dist = sqrtf(rx * rx + ry * ry + rz * rz);
    float dr = 1.0f / (dist + EPSV);
    dr = dr / (hasAny ? (float)idn : 1.0f);
    float drsum = warpSum(dr);
    float w = hasAny ? (dr / drsum) : 0.0f;

    // ---- gather features
    float g[CIN];
    {
        const float4* gp = (const float4*)(g_featg + ((size_t)b * NPTS + pos) * CIN);
        float4 f0 = __ldg(gp + 0), f1 = __ldg(gp + 1);
        float4 f2 = __ldg(gp + 2), f3 = __ldg(gp + 3);
        g[0]=f0.x; g[1]=f0.y; g[2]=f0.z; g[3]=f0.w;
        g[4]=f1.x; g[5]=f1.y; g[6]=f1.z; g[7]=f1.w;
        g[8]=f2.x; g[9]=f2.y; g[10]=f2.z; g[11]=f2.w;
        g[12]=f3.x; g[13]=f3.y; g[14]=f3.z; g[15]=f3.w;
    }

    float* fo = feat_out + (size_t)b * 96 * MQ + m;

    // ---- xyz branch: 3->32 packed fma2, then butterfly MAX fold
    {
        unsigned long long hrx = pack2(rx, rx), hry = pack2(ry, ry), hrz = pack2(rz, rz);
        float v[32];
        #pragma unroll
        for (int t = 0; t < 16; t++) {
            unsigned long long a = fma2(s_wxp[t], hrx, s_bxp[t]);
            a = fma2(s_wxp[16 + t], hry, a);
            a = fma2(s_wxp[32 + t], hrz, a);
            float xa, xb2; unpack2(xa, xb2, a);
            v[2 * t] = fmaxf(xa, 0.0f);
            v[2 * t + 1] = fmaxf(xb2, 0.0f);
        }
        {
            bool h = (lane >> 4) & 1;
            #pragma unroll
            for (int i = 0; i < 16; i++) {
                float keep = h ? v[i + 16] : v[i];
                float snd  = h ? v[i]      : v[i + 16];
                v[i] = fmaxf(keep, __shfl_xor_sync(FULLM, snd, 16));
            }
        }
        {
            bool h = (lane >> 3) & 1;
            #pragma unroll
            for (int i = 0; i < 8; i++) {
                float keep = h ? v[i + 8] : v[i];
                float snd  = h ? v[i]     : v[i + 8];
                v[i] = fmaxf(keep, __shfl_xor_sync(FULLM, snd, 8));
            }
        }
        {
            bool h = (lane >> 2) & 1;
            #pragma unroll
            for (int i = 0; i < 4; i++) {
                float keep = h ? v[i + 4] : v[i];
                float snd  = h ? v[i]     : v[i + 4];
                v[i] = fmaxf(keep, __shfl_xor_sync(FULLM, snd, 4));
            }
        }
        {
            bool h = (lane >> 1) & 1;
            #pragma unroll
            for (int i = 0; i < 2; i++) {
                float keep = h ? v[i + 2] : v[i];
                float snd  = h ? v[i]     : v[i + 2];
                v[i] = fmaxf(keep, __shfl_xor_sync(FULLM, snd, 2));
            }
        }
        {
            bool h = lane & 1;
            float keep = h ? v[1] : v[0];
            float snd  = h ? v[0] : v[1];
            v[0] = fmaxf(keep, __shfl_xor_sync(FULLM, snd, 1));
        }
        fo[(size_t)lane * MQ] = v[0];    // lane l holds channel l
    }

    // ---- layer 0: 16 -> 32, packed f32x2
    float h0[32];
    {
        unsigned long long acc0[16];
        #pragma unroll
        for (int t = 0; t < 16; t++) acc0[t] = pack2(s_b0[2 * t], s_b0[2 * t + 1]);
        #pragma unroll
        for (int c2 = 0; c2 < 8; c2++) {
            unsigned long long ha = pack2(g[2 * c2],     g[2 * c2]);
            unsigned long long hb = pack2(g[2 * c2 + 1], g[2 * c2 + 1]);
            #pragma unroll
            for (int t = 0; t < 16; t++) {
                ulonglong2 wv = s_w0p[t * 8 + c2];
                acc0[t] = fma2(wv.x, ha, acc0[t]);
                acc0[t] = fma2(wv.y, hb, acc0[t]);
            }
        }
        #pragma unroll
        for (int t = 0; t < 16; t++) {
            float a, bqq; unpack2(a, bqq, acc0[t]);
            h0[2 * t] = fmaxf(a, 0.0f);
            h0[2 * t + 1] = fmaxf(bqq, 0.0f);
        }
    }

    // ---- layer 1: 32 -> 64 in 4 chunks, packed FMA + butterfly SUM fold
    #pragma unroll
    for (int og = 0; og < 4; og++) {
        unsigned long long acc[8];
        #pragma unroll
        for (int t = 0; t < 8; t++)
            acc[t] = pack2(s_b1[og * 16 + 2 * t], s_b1[og * 16 + 2 * t + 1]);
        #pragma unroll
        for (int c2 = 0; c2 < 16; c2++) {
            unsigned long long ha = pack2(h0[2 * c2],     h0[2 * c2]);
            unsigned long long hb = pack2(h0[2 * c2 + 1], h0[2 * c2 + 1]);
            #pragma unroll
            for (int t = 0; t < 8; t++) {
                ulonglong2 wv = s_w1p[(og * 8 + t) * 16 + c2];
                acc[t] = fma2(wv.x, ha, acc[t]);
                acc[t] = fma2(wv.y, hb, acc[t]);
            }
        }
        float v[16];
        #pragma unroll
        for (int t = 0; t < 8; t++) {
            float a, bqq; unpack2(a, bqq, acc[t]);
            v[2 * t]     = w * fmaxf(a, 0.0f);
            v[2 * t + 1] = w * fmaxf(bqq, 0.0f);
        }
        #pragma unroll
        for (int i = 0; i < 16; i++) v[i] += __shfl_xor_sync(FULLM, v[i], 16);
        {
            bool h = (lane >> 3) & 1;
            #pragma unroll
            for (int i = 0; i < 8; i++) {
                float keep = h ? v[i + 8] : v[i];
                float snd  = h ? v[i]     : v[i + 8];
                v[i] = keep + __shfl_xor_sync(FULLM, snd, 8);
            }
        }
        {
            bool h = (lane >> 2) & 1;
            #pragma unroll
            for (int i = 0; i < 4; i++) {
                float keep = h ? v[i + 4] : v[i];
                float snd  = h ? v[i]     : v[i + 4];
                v[i] = keep + __shfl_xor_sync(FULLM, snd, 4);
            }
        }
        {
            bool h = (lane >> 1) & 1;
            #pragma unroll
            for (int i = 0; i < 2; i++) {
                float keep = h ? v[i + 2] : v[i];
                float snd  = h ? v[i]     : v[i + 2];
                v[i] = keep + __shfl_xor_sync(FULLM, snd, 2);
            }
        }
        {
            bool h = lane & 1;
            float keep = h ? v[1] : v[0];
            float snd  = h ? v[0] : v[1];
            v[0] = keep + __shfl_xor_sync(FULLM, snd, 1);
        }
        if (lane < 16)
            fo[(size_t)(32 + og * 16 + lane) * MQ] = v[0];
    }
}

extern "C" void kernel_launch(void* const* d_in, const int* in_sizes, int n_in,
                              void* d_out, int out_size) {
    const float* xyz      = (const float*)d_in[0];
    const float* new_xyz  = (const float*)d_in[1];
    const float* features = (const float*)d_in[2];
    const float* w0   = (const float*)d_in[3];
    const float* b0   = (const float*)d_in[4];
    const float* w1   = (const float*)d_in[5];
    const float* b1   = (const float*)d_in[6];
    const float* wxyz = (const float*)d_in[7];
    const float* bxyz = (const float*)d_in[8];

    float* out = (float*)d_out;
    long nxyz  = (long)BB * MQ * 3;
    long nfeat = (long)BB * 96 * MQ;
    float* feat_out;
    if ((long)out_size >= nxyz + nfeat) {
        cudaMemcpyAsync(out, new_xyz, nxyz * sizeof(float),
                        cudaMemcpyDeviceToDevice);
        feat_out = out + nxyz;
    } else {
        feat_out = out;
    }

    void* ptr = nullptr;
    cudaGetSymbolAddress(&ptr, g_cnt);
    cudaMemsetAsync(ptr, 0, BB * NCELL * sizeof(int));
    cudaGetSymbolAddress(&ptr, g_qcnt);
    cudaMemsetAsync(ptr, 0, BB * NCELL * sizeof(int));

    int nprep = BB * (NPTS + MQ);
    hist_kernel<<<(nprep + 255) / 256, 256>>>(xyz, new_xyz);
    scan_kernel<<<BB, 1024>>>();
    scatter_feat_kernel<<<(nprep + 255) / 256, 256>>>(xyz, new_xyz, features);
    grouper_kernel<<<NQ / 8, 256>>>(xyz, new_xyz,
                                    w0, b0, w1, b1, wxyz, bxyz, feat_out);
}

// round 14
// speedup vs baseline: 1.1573x; 1.1267x over previous
#include <cuda_runtime.h>
#include <climits>

#define BB   2
#define NPTS 16384
#define MQ   4096
#define CIN  16
#define KNB  32
#define RAD2 0.01f
#define EPSV 1e-8f
#define FULLM 0xFFFFFFFFu
#define G    10
#define NCELL (G*G*G)
#define CAP  256
#define NQ   (BB * MQ)

// merged counters: [0,BB*NCELL) = point counters, [BB*NCELL, 2*BB*NCELL) = query counters
__device__ int    g_cntall[2 * BB * NCELL];
__device__ int    g_start[BB * NCELL];
__device__ int    g_qstart[BB * NCELL];
__device__ int    g_qorder[NQ];
__device__ float4 g_pts[BB * NPTS];
__device__ float  g_featg[(size_t)BB * NPTS * CIN];   // grid-ordered [pos][16]

#define PCNT(b, c) g_cntall[(b) * NCELL + (c)]
#define QCNT(b, c) g_cntall[(BB + (b)) * NCELL + (c)]

// ---------------- packed f32x2 helpers ----------------
__device__ __forceinline__ unsigned long long fma2(unsigned long long a,
                                                   unsigned long long b,
                                                   unsigned long long c) {
    unsigned long long d;
    asm("fma.rn.f32x2 %0, %1, %2, %3;" : "=l"(d) : "l"(a), "l"(b), "l"(c));
    return d;
}
__device__ __forceinline__ unsigned long long pack2(float x, float y) {
    unsigned long long r;
    asm("mov.b64 %0, {%1,%2};" : "=l"(r) : "f"(x), "f"(y));
    return r;
}
__device__ __forceinline__ void unpack2(float& x, float& y, unsigned long long v) {
    asm("mov.b64 {%0,%1}, %2;" : "=f"(x), "=f"(y) : "l"(v));
}

__device__ __forceinline__ int cellOf(float x, float y, float z) {
    int cx = min((int)(x * (float)G), G - 1);
    int cy = min((int)(y * (float)G), G - 1);
    int cz = min((int)(z * (float)G), G - 1);
    return (cx * G + cy) * G + cz;
}

// histogram points AND queries by cell
__global__ void hist_kernel(const float* __restrict__ xyz,
                            const float* __restrict__ new_xyz) {
    int p = blockIdx.x * blockDim.x + threadIdx.x;
    if (p < BB * NPTS) {
        int b = p / NPTS;
        float x = xyz[3 * p + 0], y = xyz[3 * p + 1], z = xyz[3 * p + 2];
        atomicAdd(&PCNT(b, cellOf(x, y, z)), 1);
    } else {
        int j = p - BB * NPTS;
        if (j < NQ) {
            int b = j / MQ;
            float x = new_xyz[3 * j + 0], y = new_xyz[3 * j + 1], z = new_xyz[3 * j + 2];
            atomicAdd(&QCNT(b, cellOf(x, y, z)), 1);
        }
    }
}

// grid = 2*BB: block bb scans histogram bb (0,1 = points b0,b1; 2,3 = queries b0,b1)
__global__ void scan_kernel() {
    __shared__ int s[1024];
    int bb = blockIdx.x, i = threadIdx.x;
    int val = (i < NCELL) ? g_cntall[bb * NCELL + i] : 0;
    s[i] = val;
    __syncthreads();
    #pragma unroll
    for (int off = 1; off < 1024; off <<= 1) {
        int t = (i >= off) ? s[i - off] : 0;
        __syncthreads();
        s[i] += t;
        __syncthreads();
    }
    if (i < NCELL) {
        int excl = s[i] - val;
        if (bb < BB) g_start[bb * NCELL + i] = excl;
        else         g_qstart[(bb - BB) * NCELL + i] = excl;
        g_cntall[bb * NCELL + i] = 0;   // reuse as scatter counter
    }
}

// scatter points (with features, grid-ordered) AND query ids (cell-sorted)
__global__ void scatter_feat_kernel(const float* __restrict__ xyz,
                                    const float* __restrict__ new_xyz,
                                    const float* __restrict__ features) {
    int p = blockIdx.x * blockDim.x + threadIdx.x;
    if (p < BB * NPTS) {
        int b = p / NPTS, i = p % NPTS;
        float x = xyz[3 * p + 0], y = xyz[3 * p + 1], z = xyz[3 * p + 2];
        int c = cellOf(x, y, z);
        int pos = g_start[b * NCELL + c] + atomicAdd(&PCNT(b, c), 1);
        g_pts[b * NPTS + pos] = make_float4(x, y, z, __int_as_float(i));

        const float* fb = features + (size_t)b * CIN * NPTS + i;
        float v[CIN];
        #pragma unroll
        for (int cc = 0; cc < CIN; cc++) v[cc] = __ldg(fb + (size_t)cc * NPTS);
        float4* dst = (float4*)(g_featg + ((size_t)b * NPTS + pos) * CIN);
        dst[0] = make_float4(v[0],  v[1],  v[2],  v[3]);
        dst[1] = make_float4(v[4],  v[5],  v[6],  v[7]);
        dst[2] = make_float4(v[8],  v[9],  v[10], v[11]);
        dst[3] = make_float4(v[12], v[13], v[14], v[15]);
    } else {
        int j = p - BB * NPTS;
        if (j < NQ) {
            int b = j / MQ, m = j % MQ;
            float x = new_xyz[3 * j + 0], y = new_xyz[3 * j + 1], z = new_xyz[3 * j + 2];
            int c = cellOf(x, y, z);
            int pos = g_qstart[b * NCELL + c] + atomicAdd(&QCNT(b, c), 1);
            g_qorder[b * MQ + pos] = m;
        }
    }
}

__device__ __forceinline__ float warpSum(float v) {
    #pragma unroll
    for (int o = 16; o > 0; o >>= 1) v += __shfl_xor_sync(FULLM, v, o);
    return v;
}

__global__ __launch_bounds__(256, 4) void grouper_kernel(
    const float* __restrict__ xyz, const float* __restrict__ new_xyz,
    const float* __restrict__ w0, const float* __restrict__ b0,
    const float* __restrict__ w1, const float* __restrict__ b1,
    const float* __restrict__ wxyz, const float* __restrict__ bxyz,
    float* __restrict__ feat_out)
{
    // pair-interleaved weights for packed f32x2
    __shared__ ulonglong2 s_w0p[16 * 8];    // 2 KB
    __shared__ ulonglong2 s_w1p[32 * 16];   // 8 KB
    __shared__ unsigned long long s_wxp[48], s_bxp[16];
    __shared__ float s_b0[32], s_b1[64];
    __shared__ int   s_cand[8][CAP];

    int tid = threadIdx.x;
    {
        float* f0 = (float*)s_w0p;
        for (int e = tid; e < 512; e += 256) {
            int qq = e & 3, c2 = (e >> 2) & 7, p = e >> 5;
            f0[e] = w0[(2 * p + (qq & 1)) * 16 + 2 * c2 + (qq >> 1)];
        }
        float* f1 = (float*)s_w1p;
        for (int e = tid; e < 2048; e += 256) {
            int qq = e & 3, c2 = (e >> 2) & 15, p = e >> 6;
            f1[e] = w1[(2 * p + (qq & 1)) * 32 + 2 * c2 + (qq >> 1)];
        }
        float* fx = (float*)s_wxp;   // [d][t] pairs: (wx[2t][d], wx[2t+1][d])
        if (tid < 96) {
            int qq = tid & 1, t = (tid >> 1) & 15, d = tid >> 5;
            fx[d * 32 + t * 2 + qq] = wxyz[(2 * t + qq) * 3 + d];
        }
        float* fbx = (float*)s_bxp;
        if (tid < 32) fbx[tid] = bxyz[tid];
    }
    if (tid < 32) s_b0[tid] = b0[tid];
    if (tid < 64) s_b1[tid] = b1[tid];
    __syncthreads();

    int warp = tid >> 5, lane = tid & 31;
    int qs = blockIdx.x * 8 + warp;       // cell-sorted slot
    int b = qs / MQ;
    int m = __ldg(&g_qorder[qs]);         // original query index within batch

    const float* qp = new_xyz + ((size_t)b * MQ + m) * 3;
    float qx = __ldg(qp + 0), qy = __ldg(qp + 1), qz = __ldg(qp + 2);

    int qcx = min((int)(qx * (float)G), G - 1);
    int qcy = min((int)(qy * (float)G), G - 1);

    // ---- prefetch all 9 column ranges in parallel (lanes 0..8)
    int colS = 0, colE = 0;
    if (lane < 9) {
        int cx = qcx + lane / 3 - 1, cy = qcy + lane % 3 - 1;
        if (cx >= 0 && cx < G && cy >= 0 && cy < G) {
            float fx = fmaxf(0.f, fmaxf(cx * 0.1f - qx, qx - (cx + 1) * 0.1f));
            float fy = fmaxf(0.f, fmaxf(cy * 0.1f - qy, qy - (cy + 1) * 0.1f));
            float dxy2 = fx * fx + fy * fy;
            if (dxy2 < RAD2) {
                float rzs = sqrtf(RAD2 - dxy2) + 1e-6f;
                int zz0 = max(0, (int)((qz - rzs) * (float)G));
                int zz1 = min(G - 1, (int)((qz + rzs) * (float)G));
                int cbase = (cx * G + cy) * G;
                colS = g_start[b * NCELL + cbase + zz0];
                colE = g_start[b * NCELL + cbase + zz1] + PCNT(b, cbase + zz1);
            }
        }
    }

    // ---- candidate collection, 64 candidates per iteration
    //      key = (origIdx << 14) | gridPos; list ORDER is irrelevant (set semantics)
    int* lst = s_cand[warp];
    int cnt = 0;
    const float4* pb = g_pts + (size_t)b * NPTS;
    unsigned laneLT = (1u << lane) - 1u;

    for (int cc = 0; cc < 9; cc++) {
        int s = __shfl_sync(FULLM, colS, cc);
        int e = __shfl_sync(FULLM, colE, cc);
        for (int base = s; base < e; base += 64) {
            int i0 = base + lane, i1 = i0 + 32;
            bool hit0 = false, hit1 = false;
            int k0 = 0, k1 = 0;
            if (i0 < e) {
                float4 p = __ldg(&pb[i0]);
                float dx = p.x - qx, dy = p.y - qy, dz = p.z - qz;
                hit0 = (dx * dx + dy * dy + dz * dz) < RAD2;
                k0 = (__float_as_int(p.w) << 14) | i0;
            }
            if (i1 < e) {
                float4 p = __ldg(&pb[i1]);
                float dx = p.x - qx, dy = p.y - qy, dz = p.z - qz;
                hit1 = (dx * dx + dy * dy + dz * dz) < RAD2;
                k1 = (__float_as_int(p.w) << 14) | i1;
            }
            unsigned mk0 = __ballot_sync(FULLM, hit0);
            unsigned mk1 = __ballot_sync(FULLM, hit1);
            if (hit0) {
                int pos = cnt + __popc(mk0 & laneLT);
                if (pos < CAP) lst[pos] = k0;
            }
            cnt += __popc(mk0);
            if (hit1) {
                int pos = cnt + __popc(mk1 & laneLT);
                if (pos < CAP) lst[pos] = k1;
            }
            cnt += __popc(mk1);
        }
    }
    cnt = min(cnt, CAP);
    __syncwarp();

    // ---- load candidates (orig indices DISTINCT)
    int c[8];
    #pragma unroll
    for (int j = 0; j < 8; j++) {
        int p = lane + 32 * j;
        c[j] = (p < cnt) ? lst[p] : INT_MAX;
    }
    int mn8 = c[0];
    #pragma unroll
    for (int j = 1; j < 8; j++) mn8 = min(mn8, c[j]);
    int firstKey = __reduce_min_sync(FULLM, mn8);
    bool hasAny = (cnt > 0);

    int sel;
    if (cnt > KNB) {
        int o[8];
        #pragma unroll
        for (int j = 0; j < 8; j++) o[j] = c[j] >> 14;   // INT_MAX>>14 stays huge
        int lo = 0, hi = NPTS - 1;                       // threshold on orig index
        while (lo < hi) {
            int mid = (lo + hi) >> 1;
            int lc = 0;
            #pragma unroll
            for (int j = 0; j < 8; j++) lc += (o[j] <= mid);
            int tot = __reduce_add_sync(FULLM, (unsigned)lc);
            if (tot >= KNB) hi = mid; else lo = mid + 1;
        }
        int T = lo;
        __syncwarp();
        int base2 = 0;
        #pragma unroll
        for (int j = 0; j < 8; j++) {
            bool sflag = (o[j] <= T);
            unsigned mk = __ballot_sync(FULLM, sflag);
            if (sflag) lst[base2 + __popc(mk & laneLT)] = c[j];
            base2 += __popc(mk);
        }
        __syncwarp();
        sel = lst[lane];
    } else {
        sel = (lane < cnt) ? lst[lane] : firstKey;       // pad with smallest
    }

    int idn = __popc(__match_any_sync(FULLM, sel));
    int pos = sel & (NPTS - 1);

    // ---- coords from grid-ordered points
    float px, py, pz;
    if (hasAny) {
        float4 p = __ldg(&pb[pos]);
        px = p.x; py = p.y; pz = p.z;
    } else {
        const float* xb = xyz + (size_t)b * NPTS * 3;    // reference: idx = 0
        px = __ldg(xb + 0); py = __ldg(xb + 1); pz = __ldg(xb + 2);
    }
    float rx = px - qx, ry = py - qy, rz = pz - qz;
    float dist = sqrtf(rx * rx + ry * ry + rz * rz);
    float dr = 1.0f / (dist + EPSV);
    dr = dr / (hasAny ? (float)idn : 1.0f);
    float drsum = warpSum(dr);
    float w = hasAny ? (dr / drsum) : 0.0f;

    // ---- gather features
    float g[CIN];
    {
        const float4* gp = (const float4*)(g_featg + ((size_t)b * NPTS + pos) * CIN);
        float4 f0 = __ldg(gp + 0), f1 = __ldg(gp + 1);
        float4 f2 = __ldg(gp + 2), f3 = __ldg(gp + 3);
        g[0]=f0.x; g[1]=f0.y; g[2]=f0.z; g[3]=f0.w;
        g[4]=f1.x; g[5]=f1.y; g[6]=f1.z; g[7]=f1.w;
        g[8]=f2.x; g[9]=f2.y; g[10]=f2.z; g[11]=f2.w;
        g[12]=f3.x; g[13]=f3.y; g[14]=f3.z; g[15]=f3.w;
    }

    float* fo = feat_out + (size_t)b * 96 * MQ + m;

    // ---- xyz branch: 3->32 packed fma2, then butterfly MAX fold
    {
        unsigned long long hrx = pack2(rx, rx), hry = pack2(ry, ry), hrz = pack2(rz, rz);
        float v[32];
        #pragma unroll
        for (int t = 0; t < 16; t++) {
            unsigned long long a = fma2(s_wxp[t], hrx, s_bxp[t]);
            a = fma2(s_wxp[16 + t], hry, a);
            a = fma2(s_wxp[32 + t], hrz, a);
            float xa, xb2; unpack2(xa, xb2, a);
            v[2 * t] = fmaxf(xa, 0.0f);
            v[2 * t + 1] = fmaxf(xb2, 0.0f);
        }
        {
            bool h = (lane >> 4) & 1;
            #pragma unroll
            for (int i = 0; i < 16; i++) {
                float keep = h ? v[i + 16] : v[i];
                float snd  = h ? v[i]      : v[i + 16];
                v[i] = fmaxf(keep, __shfl_xor_sync(FULLM, snd, 16));
            }
        }
        {
            bool h = (lane >> 3) & 1;
            #pragma unroll
            for (int i = 0; i < 8; i++) {
                float keep = h ? v[i + 8] : v[i];
                float snd  = h ? v[i]     : v[i + 8];
                v[i] = fmaxf(keep, __shfl_xor_sync(FULLM, snd, 8));
            }
        }
        {
            bool h = (lane >> 2) & 1;
            #pragma unroll
            for (int i = 0; i < 4; i++) {
                float keep = h ? v[i + 4] : v[i];
                float snd  = h ? v[i]     : v[i + 4];
                v[i] = fmaxf(keep, __shfl_xor_sync(FULLM, snd, 4));
            }
        }
        {
            bool h = (lane >> 1) & 1;
            #pragma unroll
            for (int i = 0; i < 2; i++) {
                float keep = h ? v[i + 2] : v[i];
                float snd  = h ? v[i]     : v[i + 2];
                v[i] = fmaxf(keep, __shfl_xor_sync(FULLM, snd, 2));
            }
        }
        {
            bool h = lane & 1;
            float keep = h ? v[1] : v[0];
            float snd  = h ? v[0] : v[1];
            v[0] = fmaxf(keep, __shfl_xor_sync(FULLM, snd, 1));
        }
        fo[(size_t)lane * MQ] = v[0];    // lane l holds channel l
    }

    // ---- layer 0: 16 -> 32, packed f32x2
    float h0[32];
    {
        unsigned long long acc0[16];
        #pragma unroll
        for (int t = 0; t < 16; t++) acc0[t] = pack2(s_b0[2 * t], s_b0[2 * t + 1]);
        #pragma unroll
        for (int c2 = 0; c2 < 8; c2++) {
            unsigned long long ha = pack2(g[2 * c2],     g[2 * c2]);
            unsigned long long hb = pack2(g[2 * c2 + 1], g[2 * c2 + 1]);
            #pragma unroll
            for (int t = 0; t < 16; t++) {
                ulonglong2 wv = s_w0p[t * 8 + c2];
                acc0[t] = fma2(wv.x, ha, acc0[t]);
                acc0[t] = fma2(wv.y, hb, acc0[t]);
            }
        }
        #pragma unroll
        for (int t = 0; t < 16; t++) {
            float a, bqq; unpack2(a, bqq, acc0[t]);
            h0[2 * t] = fmaxf(a, 0.0f);
            h0[2 * t + 1] = fmaxf(bqq, 0.0f);
        }
    }

    // ---- layer 1: 32 -> 64 in 4 chunks, packed FMA + butterfly SUM fold
    #pragma unroll
    for (int og = 0; og < 4; og++) {
        unsigned long long acc[8];
        #pragma unroll
        for (int t = 0; t < 8; t++)
            acc[t] = pack2(s_b1[og * 16 + 2 * t], s_b1[og * 16 + 2 * t + 1]);
        #pragma unroll
        for (int c2 = 0; c2 < 16; c2++) {
            unsigned long long ha = pack2(h0[2 * c2],     h0[2 * c2]);
            unsigned long long hb = pack2(h0[2 * c2 + 1], h0[2 * c2 + 1]);
            #pragma unroll
            for (int t = 0; t < 8; t++) {
                ulonglong2 wv = s_w1p[(og * 8 + t) * 16 + c2];
                acc[t] = fma2(wv.x, ha, acc[t]);
                acc[t] = fma2(wv.y, hb, acc[t]);
            }
        }
        float v[16];
        #pragma unroll
        for (int t = 0; t < 8; t++) {
            float a, bqq; unpack2(a, bqq, acc[t]);
            v[2 * t]     = w * fmaxf(a, 0.0f);
            v[2 * t + 1] = w * fmaxf(bqq, 0.0f);
        }
        #pragma unroll
        for (int i = 0; i < 16; i++) v[i] += __shfl_xor_sync(FULLM, v[i], 16);
        {
            bool h = (lane >> 3) & 1;
            #pragma unroll
            for (int i = 0; i < 8; i++) {
                float keep = h ? v[i + 8] : v[i];
                float snd  = h ? v[i]     : v[i + 8];
                v[i] = keep + __shfl_xor_sync(FULLM, snd, 8);
            }
        }
        {
            bool h = (lane >> 2) & 1;
            #pragma unroll
            for (int i = 0; i < 4; i++) {
                float keep = h ? v[i + 4] : v[i];
                float snd  = h ? v[i]     : v[i + 4];
                v[i] = keep + __shfl_xor_sync(FULLM, snd, 4);
            }
        }
        {
            bool h = (lane >> 1) & 1;
            #pragma unroll
            for (int i = 0; i < 2; i++) {
                float keep = h ? v[i + 2] : v[i];
                float snd  = h ? v[i]     : v[i + 2];
                v[i] = keep + __shfl_xor_sync(FULLM, snd, 2);
            }
        }
        {
            bool h = lane & 1;
            float keep = h ? v[1] : v[0];
            float snd  = h ? v[0] : v[1];
            v[0] = keep + __shfl_xor_sync(FULLM, snd, 1);
        }
        if (lane < 16)
            fo[(size_t)(32 + og * 16 + lane) * MQ] = v[0];
    }
}

extern "C" void kernel_launch(void* const* d_in, const int* in_sizes, int n_in,
                              void* d_out, int out_size) {
    const float* xyz      = (const float*)d_in[0];
    const float* new_xyz  = (const float*)d_in[1];
    const float* features = (const float*)d_in[2];
    const float* w0   = (const float*)d_in[3];
    const float* b0   = (const float*)d_in[4];
    const float* w1   = (const float*)d_in[5];
    const float* b1   = (const float*)d_in[6];
    const float* wxyz = (const float*)d_in[7];
    const float* bxyz = (const float*)d_in[8];

    float* out = (float*)d_out;
    long nxyz  = (long)BB * MQ * 3;
    long nfeat = (long)BB * 96 * MQ;
    float* feat_out;
    if ((long)out_size >= nxyz + nfeat) {
        cudaMemcpyAsync(out, new_xyz, nxyz * sizeof(float),
                        cudaMemcpyDeviceToDevice);
        feat_out = out + nxyz;
    } else {
        feat_out = out;
    }

    void* ptr = nullptr;
    cudaGetSymbolAddress(&ptr, g_cntall);
    cudaMemsetAsync(ptr, 0, 2 * BB * NCELL * sizeof(int));

    int nprep = BB * (NPTS + MQ);
    hist_kernel<<<(nprep + 255) / 256, 256>>>(xyz, new_xyz);
    scan_kernel<<<2 * BB, 1024>>>();
    scatter_feat_kernel<<<(nprep + 255) / 256, 256>>>(xyz, new_xyz, features);
    grouper_kernel<<<NQ / 8, 256>>>(xyz, new_xyz,
                                    w0, b0, w1, b1, wxyz, bxyz, feat_out);
}